// round 10
// baseline (speedup 1.0000x reference)
#include <cuda_runtime.h>
#include <cuda_bf16.h>

#define N_NODES 50000
#define N_EDGES 800000
#define D 64

// ---- device-global scratch (no allocations allowed) ----
__device__ __align__(16) float g_denom[N_NODES];
__device__ __align__(16) float g_hunnorm[N_NODES * D];   // un-normalized msg sums

// ---------------------------------------------------------------------------
// Fused edge kernel, 4 edges per half-warp (ILP=4):
//   8 independent 16B loads in flight, 4 interleaved shfl-reduce chains,
//   ex = exp(dot);  hunnorm[dst] += ex*hv (red.v4);  denom[dst] += ex.
// Warp covers 8 consecutive edges -> e stream stays fully sequential (2KB/warp).
// Normalization deferred to the GEMM.
// ---------------------------------------------------------------------------
__global__ void __launch_bounds__(256) kgcn_edge_kernel(
        const float* __restrict__ h_src,
        const float* __restrict__ e,
        const int* __restrict__ src,
        const int* __restrict__ dst) {
    int tid = blockIdx.x * blockDim.x + threadIdx.x;
    int grp = tid >> 4;          // half-warp group id (200000 groups exactly)
    int sub = tid & 15;
    int eb  = grp * 4;

    int s0 = src[eb + 0], s1 = src[eb + 1], s2 = src[eb + 2], s3 = src[eb + 3];
    int d0 = dst[eb + 0], d1 = dst[eb + 1], d2 = dst[eb + 2], d3 = dst[eb + 3];

    const float4* h4 = reinterpret_cast<const float4*>(h_src);
    const float4* e4 = reinterpret_cast<const float4*>(e);

    float4 ev0 = e4[(size_t)(eb + 0) * 16 + sub];
    float4 ev1 = e4[(size_t)(eb + 1) * 16 + sub];
    float4 ev2 = e4[(size_t)(eb + 2) * 16 + sub];
    float4 ev3 = e4[(size_t)(eb + 3) * 16 + sub];
    float4 hv0 = h4[(size_t)s0 * 16 + sub];
    float4 hv1 = h4[(size_t)s1 * 16 + sub];
    float4 hv2 = h4[(size_t)s2 * 16 + sub];
    float4 hv3 = h4[(size_t)s3 * 16 + sub];

    float t0 = hv0.x * ev0.x + hv0.y * ev0.y + hv0.z * ev0.z + hv0.w * ev0.w;
    float t1 = hv1.x * ev1.x + hv1.y * ev1.y + hv1.z * ev1.z + hv1.w * ev1.w;
    float t2 = hv2.x * ev2.x + hv2.y * ev2.y + hv2.z * ev2.z + hv2.w * ev2.w;
    float t3 = hv3.x * ev3.x + hv3.y * ev3.y + hv3.z * ev3.z + hv3.w * ev3.w;

    // 4 interleaved xor-reductions: independent chains hide SHFL latency
    #pragma unroll
    for (int o = 1; o < 16; o <<= 1) {
        t0 += __shfl_xor_sync(0xffffffffu, t0, o);
        t1 += __shfl_xor_sync(0xffffffffu, t1, o);
        t2 += __shfl_xor_sync(0xffffffffu, t2, o);
        t3 += __shfl_xor_sync(0xffffffffu, t3, o);
    }

    float ex0 = __expf(t0);
    float ex1 = __expf(t1);
    float ex2 = __expf(t2);
    float ex3 = __expf(t3);

    float* a0 = &g_hunnorm[(size_t)d0 * D + sub * 4];
    float* a1 = &g_hunnorm[(size_t)d1 * D + sub * 4];
    float* a2 = &g_hunnorm[(size_t)d2 * D + sub * 4];
    float* a3 = &g_hunnorm[(size_t)d3 * D + sub * 4];
    asm volatile("red.global.add.v4.f32 [%0], {%1, %2, %3, %4};"
                 :: "l"(a0), "f"(ex0 * hv0.x), "f"(ex0 * hv0.y),
                    "f"(ex0 * hv0.z), "f"(ex0 * hv0.w) : "memory");
    asm volatile("red.global.add.v4.f32 [%0], {%1, %2, %3, %4};"
                 :: "l"(a1), "f"(ex1 * hv1.x), "f"(ex1 * hv1.y),
                    "f"(ex1 * hv1.z), "f"(ex1 * hv1.w) : "memory");
    asm volatile("red.global.add.v4.f32 [%0], {%1, %2, %3, %4};"
                 :: "l"(a2), "f"(ex2 * hv2.x), "f"(ex2 * hv2.y),
                    "f"(ex2 * hv2.z), "f"(ex2 * hv2.w) : "memory");
    asm volatile("red.global.add.v4.f32 [%0], {%1, %2, %3, %4};"
                 :: "l"(a3), "f"(ex3 * hv3.x), "f"(ex3 * hv3.y),
                    "f"(ex3 * hv3.z), "f"(ex3 * hv3.w) : "memory");
    if (sub == 0) {
        atomicAdd(&g_denom[d0], ex0);
        atomicAdd(&g_denom[d1], ex1);
        atomicAdd(&g_denom[d2], ex2);
        atomicAdd(&g_denom[d3], ex3);
    }
}

// ---------------------------------------------------------------------------
// Output GEMM: out = concat(h_dst, hunnorm/denom) @ W^T + b
// Block: 256 threads -> 64-node x 64-col tile; thread: 4 nodes x 4 cols.
// Normalization folded into the staging of chunks 2-3.
// ---------------------------------------------------------------------------
#define HS_STRIDE 33
__global__ void __launch_bounds__(256) kgcn_out_kernel(
        const float* __restrict__ h_dst,
        const float* __restrict__ W,
        const float* __restrict__ b,
        float* __restrict__ out) {
    __shared__ float W_s[128 * 64];          // [k][j] transposed, 32KB
    __shared__ float h_s[64 * HS_STRIDE];    // [local node][kk], padded

    const int tid = threadIdx.x;
    for (int i = tid; i < 64 * 128; i += 256) {
        int j = i >> 7;
        int k = i & 127;
        W_s[k * 64 + j] = W[i];
    }

    const int tx = tid & 15;      // cols 4*tx..4*tx+3
    const int ty = tid >> 4;      // nodes 4*ty..4*ty+3
    const int node0 = blockIdx.x * 64;

    float acc[4][4];
    #pragma unroll
    for (int n = 0; n < 4; n++)
        acc[n][0] = acc[n][1] = acc[n][2] = acc[n][3] = 0.f;

    #pragma unroll
    for (int c = 0; c < 4; c++) {
        const float* srcp = (c < 2) ? h_dst : g_hunnorm;
        const int kof4 = (c & 1) * 8;

        __syncthreads();
        #pragma unroll
        for (int r = 0; r < 2; r++) {
            int idx = tid + r * 256;    // 0..511
            int n   = idx >> 3;
            int q   = idx & 7;
            int gn  = node0 + n;
            float4 v = make_float4(0.f, 0.f, 0.f, 0.f);
            if (gn < N_NODES) {
                v = reinterpret_cast<const float4*>(srcp)[(size_t)gn * 16 + kof4 + q];
                if (c >= 2) {
                    float dn = g_denom[gn];
                    float inv = (dn != 0.f) ? (1.0f / dn) : 0.f;  // edge-less -> 0
                    v.x *= inv; v.y *= inv; v.z *= inv; v.w *= inv;
                }
            }
            int base = n * HS_STRIDE + q * 4;
            h_s[base + 0] = v.x; h_s[base + 1] = v.y;
            h_s[base + 2] = v.z; h_s[base + 3] = v.w;
        }
        __syncthreads();

        const float* Wrow = &W_s[(c * 32) * 64 + 4 * tx];
        #pragma unroll 8
        for (int kk = 0; kk < 32; kk++) {
            float4 w = *reinterpret_cast<const float4*>(Wrow + kk * 64);
            #pragma unroll
            for (int n = 0; n < 4; n++) {
                float hv = h_s[(4 * ty + n) * HS_STRIDE + kk];
                acc[n][0] = fmaf(hv, w.x, acc[n][0]);
                acc[n][1] = fmaf(hv, w.y, acc[n][1]);
                acc[n][2] = fmaf(hv, w.z, acc[n][2]);
                acc[n][3] = fmaf(hv, w.w, acc[n][3]);
            }
        }
    }

    float4 bb = *reinterpret_cast<const float4*>(&b[4 * tx]);
    #pragma unroll
    for (int n = 0; n < 4; n++) {
        int gn = node0 + 4 * ty + n;
        if (gn < N_NODES) {
            float4 o = make_float4(acc[n][0] + bb.x, acc[n][1] + bb.y,
                                   acc[n][2] + bb.z, acc[n][3] + bb.w);
            reinterpret_cast<float4*>(out)[(size_t)gn * 16 + tx] = o;
        }
    }
}

// ---------------------------------------------------------------------------
// Launch.  Inputs: 0 h_src, 1 h_dst, 2 e, 3 src, 4 dst, 5 W, 6 b
// Zeroing done with cudaMemsetAsync (graph-capturable memset nodes — no
// kernel-launch floor, full fill bandwidth).
// ---------------------------------------------------------------------------
extern "C" void kernel_launch(void* const* d_in, const int* in_sizes, int n_in,
                              void* d_out, int out_size) {
    const float* h_src = (const float*)d_in[0];
    const float* h_dst = (const float*)d_in[1];
    const float* e     = (const float*)d_in[2];
    const int*   src   = (const int*)d_in[3];
    const int*   dst   = (const int*)d_in[4];
    const float* W     = (const float*)d_in[5];
    const float* b     = (const float*)d_in[6];
    float* out = (float*)d_out;

    void* p_hunnorm = nullptr;
    void* p_denom   = nullptr;
    cudaGetSymbolAddress(&p_hunnorm, g_hunnorm);
    cudaGetSymbolAddress(&p_denom,   g_denom);
    cudaMemsetAsync(p_hunnorm, 0, sizeof(float) * N_NODES * D);
    cudaMemsetAsync(p_denom,   0, sizeof(float) * N_NODES);

    // 200000 half-warp groups * 4 edges; 16 groups per 256-thread block
    kgcn_edge_kernel<<<12500, 256>>>(h_src, e, src, dst);
    kgcn_out_kernel<<<(N_NODES + 63) / 64, 256>>>(h_dst, W, b, out);
}

// round 11
// speedup vs baseline: 1.1593x; 1.1593x over previous
#include <cuda_runtime.h>
#include <cuda_bf16.h>

#define N_NODES 50000
#define N_EDGES 800000
#define D 64

// ---- device-global scratch (no allocations allowed) ----
__device__ __align__(16) float g_denom[N_NODES];
__device__ __align__(16) float g_hunnorm[N_NODES * D];   // un-normalized msg sums

// ---------------------------------------------------------------------------
// Fused edge kernel, 4 edges per half-warp (ILP=4):
//   8 independent 16B loads in flight, 4 interleaved shfl-reduce chains,
//   ex = exp(dot);  hunnorm[dst] += ex*hv (red.v4);  denom[dst] += ex.
// ---------------------------------------------------------------------------
__global__ void __launch_bounds__(256) kgcn_edge_kernel(
        const float* __restrict__ h_src,
        const float* __restrict__ e,
        const int* __restrict__ src,
        const int* __restrict__ dst) {
    int tid = blockIdx.x * blockDim.x + threadIdx.x;
    int grp = tid >> 4;          // half-warp group id (200000 groups exactly)
    int sub = tid & 15;
    int eb  = grp * 4;

    int s0 = src[eb + 0], s1 = src[eb + 1], s2 = src[eb + 2], s3 = src[eb + 3];
    int d0 = dst[eb + 0], d1 = dst[eb + 1], d2 = dst[eb + 2], d3 = dst[eb + 3];

    const float4* h4 = reinterpret_cast<const float4*>(h_src);
    const float4* e4 = reinterpret_cast<const float4*>(e);

    float4 ev0 = e4[(size_t)(eb + 0) * 16 + sub];
    float4 ev1 = e4[(size_t)(eb + 1) * 16 + sub];
    float4 ev2 = e4[(size_t)(eb + 2) * 16 + sub];
    float4 ev3 = e4[(size_t)(eb + 3) * 16 + sub];
    float4 hv0 = h4[(size_t)s0 * 16 + sub];
    float4 hv1 = h4[(size_t)s1 * 16 + sub];
    float4 hv2 = h4[(size_t)s2 * 16 + sub];
    float4 hv3 = h4[(size_t)s3 * 16 + sub];

    float t0 = hv0.x * ev0.x + hv0.y * ev0.y + hv0.z * ev0.z + hv0.w * ev0.w;
    float t1 = hv1.x * ev1.x + hv1.y * ev1.y + hv1.z * ev1.z + hv1.w * ev1.w;
    float t2 = hv2.x * ev2.x + hv2.y * ev2.y + hv2.z * ev2.z + hv2.w * ev2.w;
    float t3 = hv3.x * ev3.x + hv3.y * ev3.y + hv3.z * ev3.z + hv3.w * ev3.w;

    #pragma unroll
    for (int o = 1; o < 16; o <<= 1) {
        t0 += __shfl_xor_sync(0xffffffffu, t0, o);
        t1 += __shfl_xor_sync(0xffffffffu, t1, o);
        t2 += __shfl_xor_sync(0xffffffffu, t2, o);
        t3 += __shfl_xor_sync(0xffffffffu, t3, o);
    }

    float ex0 = __expf(t0);
    float ex1 = __expf(t1);
    float ex2 = __expf(t2);
    float ex3 = __expf(t3);

    float* a0 = &g_hunnorm[(size_t)d0 * D + sub * 4];
    float* a1 = &g_hunnorm[(size_t)d1 * D + sub * 4];
    float* a2 = &g_hunnorm[(size_t)d2 * D + sub * 4];
    float* a3 = &g_hunnorm[(size_t)d3 * D + sub * 4];
    asm volatile("red.global.add.v4.f32 [%0], {%1, %2, %3, %4};"
                 :: "l"(a0), "f"(ex0 * hv0.x), "f"(ex0 * hv0.y),
                    "f"(ex0 * hv0.z), "f"(ex0 * hv0.w) : "memory");
    asm volatile("red.global.add.v4.f32 [%0], {%1, %2, %3, %4};"
                 :: "l"(a1), "f"(ex1 * hv1.x), "f"(ex1 * hv1.y),
                    "f"(ex1 * hv1.z), "f"(ex1 * hv1.w) : "memory");
    asm volatile("red.global.add.v4.f32 [%0], {%1, %2, %3, %4};"
                 :: "l"(a2), "f"(ex2 * hv2.x), "f"(ex2 * hv2.y),
                    "f"(ex2 * hv2.z), "f"(ex2 * hv2.w) : "memory");
    asm volatile("red.global.add.v4.f32 [%0], {%1, %2, %3, %4};"
                 :: "l"(a3), "f"(ex3 * hv3.x), "f"(ex3 * hv3.y),
                    "f"(ex3 * hv3.z), "f"(ex3 * hv3.w) : "memory");
    if (sub == 0) {
        atomicAdd(&g_denom[d0], ex0);
        atomicAdd(&g_denom[d1], ex1);
        atomicAdd(&g_denom[d2], ex2);
        atomicAdd(&g_denom[d3], ex3);
    }
}

// ---------------------------------------------------------------------------
// Output GEMM v3: out = concat(h_dst, hunnorm/denom) @ W^T + b
// Block: 256 threads -> 128-node x 64-col tile; thread: 8 nodes x 4 cols.
// h_s staged TRANSPOSED [kk][node]: inner loop per kk = 3x LDS128 (1 W slice
// + 2 broadcast 4-node slices) + 32 FMA -> ~91% FMA issues, 32-deep ILP.
// smem: W_s 32KB + h_s 32*132*4 = 16.5KB = 48.5KB -> all 391 blocks resident
// in one wave (<= 4 blocks/SM).
// ---------------------------------------------------------------------------
#define HT_STRIDE 132   // 128 + 4 pad, multiple of 4 for float4 alignment
__global__ void __launch_bounds__(256) kgcn_out_kernel(
        const float* __restrict__ h_dst,
        const float* __restrict__ W,
        const float* __restrict__ b,
        float* __restrict__ out) {
    __shared__ float W_s[128 * 64];          // [k][j] transposed, 32KB
    __shared__ float h_s[32 * HT_STRIDE];    // [kk][node], padded

    const int tid = threadIdx.x;
    for (int i = tid; i < 64 * 128; i += 256) {
        int j = i >> 7;     // out col
        int k = i & 127;    // in  idx
        W_s[k * 64 + j] = W[i];
    }

    const int tx = tid & 15;      // cols  4*tx .. 4*tx+3
    const int ty = tid >> 4;      // nodes 8*ty .. 8*ty+7
    const int node0 = blockIdx.x * 128;

    float acc[8][4];
    #pragma unroll
    for (int n = 0; n < 8; n++)
        acc[n][0] = acc[n][1] = acc[n][2] = acc[n][3] = 0.f;

    #pragma unroll
    for (int c = 0; c < 4; c++) {
        const float* srcp = (c < 2) ? h_dst : g_hunnorm;
        const int kof4 = (c & 1) * 8;

        __syncthreads();   // c==0: covers W_s; c>0: prev chunk readers done
        // Stage 128 nodes x 32 k, transposed: 1024 float4 gmem loads, 4/thread.
        #pragma unroll
        for (int r = 0; r < 4; r++) {
            int idx = tid + r * 256;    // 0..1023
            int n   = idx >> 3;         // local node 0..127
            int q   = idx & 7;          // float4 k-slot 0..7
            int gn  = node0 + n;
            float4 v = make_float4(0.f, 0.f, 0.f, 0.f);
            if (gn < N_NODES) {
                v = reinterpret_cast<const float4*>(srcp)[(size_t)gn * 16 + kof4 + q];
                if (c >= 2) {
                    float dn = g_denom[gn];
                    float inv = (dn != 0.f) ? (1.0f / dn) : 0.f;  // edge-less -> 0
                    v.x *= inv; v.y *= inv; v.z *= inv; v.w *= inv;
                }
            }
            h_s[(q * 4 + 0) * HT_STRIDE + n] = v.x;
            h_s[(q * 4 + 1) * HT_STRIDE + n] = v.y;
            h_s[(q * 4 + 2) * HT_STRIDE + n] = v.z;
            h_s[(q * 4 + 3) * HT_STRIDE + n] = v.w;
        }
        __syncthreads();

        const float* Wrow = &W_s[(c * 32) * 64 + 4 * tx];
        #pragma unroll 8
        for (int kk = 0; kk < 32; kk++) {
            float4 w  = *reinterpret_cast<const float4*>(Wrow + kk * 64);
            float4 ha = *reinterpret_cast<const float4*>(&h_s[kk * HT_STRIDE + 8 * ty]);
            float4 hb = *reinterpret_cast<const float4*>(&h_s[kk * HT_STRIDE + 8 * ty + 4]);
            float hn[8] = {ha.x, ha.y, ha.z, ha.w, hb.x, hb.y, hb.z, hb.w};
            #pragma unroll
            for (int n = 0; n < 8; n++) {
                acc[n][0] = fmaf(hn[n], w.x, acc[n][0]);
                acc[n][1] = fmaf(hn[n], w.y, acc[n][1]);
                acc[n][2] = fmaf(hn[n], w.z, acc[n][2]);
                acc[n][3] = fmaf(hn[n], w.w, acc[n][3]);
            }
        }
    }

    float4 bb = *reinterpret_cast<const float4*>(&b[4 * tx]);
    #pragma unroll
    for (int n = 0; n < 8; n++) {
        int gn = node0 + 8 * ty + n;
        if (gn < N_NODES) {
            float4 o = make_float4(acc[n][0] + bb.x, acc[n][1] + bb.y,
                                   acc[n][2] + bb.z, acc[n][3] + bb.w);
            reinterpret_cast<float4*>(out)[(size_t)gn * 16 + tx] = o;
        }
    }
}

// ---------------------------------------------------------------------------
// Launch.  Inputs: 0 h_src, 1 h_dst, 2 e, 3 src, 4 dst, 5 W, 6 b
// ---------------------------------------------------------------------------
extern "C" void kernel_launch(void* const* d_in, const int* in_sizes, int n_in,
                              void* d_out, int out_size) {
    const float* h_src = (const float*)d_in[0];
    const float* h_dst = (const float*)d_in[1];
    const float* e     = (const float*)d_in[2];
    const int*   src   = (const int*)d_in[3];
    const int*   dst   = (const int*)d_in[4];
    const float* W     = (const float*)d_in[5];
    const float* b     = (const float*)d_in[6];
    float* out = (float*)d_out;

    void* p_hunnorm = nullptr;
    void* p_denom   = nullptr;
    cudaGetSymbolAddress(&p_hunnorm, g_hunnorm);
    cudaGetSymbolAddress(&p_denom,   g_denom);
    cudaMemsetAsync(p_hunnorm, 0, sizeof(float) * N_NODES * D);
    cudaMemsetAsync(p_denom,   0, sizeof(float) * N_NODES);

    // 200000 half-warp groups * 4 edges; 16 groups per 256-thread block
    kgcn_edge_kernel<<<12500, 256>>>(h_src, e, src, dst);
    // 391 blocks of 128 nodes — single resident wave
    kgcn_out_kernel<<<(N_NODES + 127) / 128, 256>>>(h_dst, W, b, out);
}